// round 16
// baseline (speedup 1.0000x reference)
#include <cuda_runtime.h>
#include <cuda_bf16.h>
#include <mma.h>
#include <cstdint>
#include <cstddef>

using namespace nvcuda;

#define B_   2
#define S_   2048
#define H_   16
#define D_   64
#define HID  1024
#define MROWS (B_*S_)          // 4096
#define XN (MROWS*HID)         // 4,194,304
#define WN (H_*HID*D_)         // 1,048,576

// ---------------- global scratch (static; no allocations) -----------------
__device__ __nv_bfloat16 iq_hi[XN], iq_lo[XN], ik_hi[XN], ik_lo[XN], iv_hi[XN], iv_lo[XN];
__device__ __nv_bfloat16 wq_hi[WN], wq_lo[WN], wk_hi[WN], wk_lo[WN], wv_hi[WN], wv_lo[WN];
__device__ __nv_bfloat16 wo_hi[WN], wo_lo[WN];
__device__ __nv_bfloat16 pq_hi[XN], pq_lo[XN], pk_hi[XN], pk_lo[XN], pv_hi[XN], pv_lo[XN];
__device__ __nv_bfloat16 cat_hi[XN], cat_lo[XN];
__device__ float g_invsum[(size_t)B_*H_*S_];

// ---------------- wmma fragment types (proj / outproj) --------------------
typedef wmma::fragment<wmma::matrix_a, 16, 16, 16, __nv_bfloat16, wmma::row_major> ABf;
typedef wmma::fragment<wmma::matrix_b, 16, 16, 16, __nv_bfloat16, wmma::row_major> BBfR;
typedef wmma::fragment<wmma::accumulator, 16, 16, 16, float> CBf;

__device__ __forceinline__ void split2(float x, __nv_bfloat16& hi, __nv_bfloat16& lo) {
    hi = __float2bfloat16(x);
    lo = __float2bfloat16(x - __bfloat162float(hi));
}

// ---------------- cp.async helpers ----------------------------------------
__device__ __forceinline__ void cp16(uint32_t saddr, const void* gaddr) {
    asm volatile("cp.async.cg.shared.global [%0], [%1], 16;\n" :: "r"(saddr), "l"(gaddr));
}
#define CP_COMMIT() asm volatile("cp.async.commit_group;\n" ::: "memory")
#define CP_WAIT1()  asm volatile("cp.async.wait_group 1;\n" ::: "memory")
#define CP_WAIT0()  asm volatile("cp.async.wait_group 0;\n" ::: "memory")

__device__ __forceinline__ uint32_t smem_u32(const void* p) {
    uint32_t a;
    asm("{ .reg .u64 t; cvta.to.shared.u64 t, %1; cvt.u32.u64 %0, t; }" : "=r"(a) : "l"(p));
    return a;
}

// ---------------- raw mma helpers (attn) -----------------------------------
__device__ __forceinline__ void ldsm4(uint32_t& r0, uint32_t& r1, uint32_t& r2, uint32_t& r3, uint32_t a) {
    asm volatile("ldmatrix.sync.aligned.m8n8.x4.shared.b16 {%0,%1,%2,%3}, [%4];"
                 : "=r"(r0), "=r"(r1), "=r"(r2), "=r"(r3) : "r"(a));
}
__device__ __forceinline__ void ldsm4t(uint32_t& r0, uint32_t& r1, uint32_t& r2, uint32_t& r3, uint32_t a) {
    asm volatile("ldmatrix.sync.aligned.m8n8.x4.trans.shared.b16 {%0,%1,%2,%3}, [%4];"
                 : "=r"(r0), "=r"(r1), "=r"(r2), "=r"(r3) : "r"(a));
}
__device__ __forceinline__ void mma16816(float* d, const uint32_t* a, uint32_t b0, uint32_t b1) {
    asm volatile("mma.sync.aligned.m16n8k16.row.col.f32.bf16.bf16.f32 "
                 "{%0,%1,%2,%3}, {%4,%5,%6,%7}, {%8,%9}, {%0,%1,%2,%3};"
                 : "+f"(d[0]), "+f"(d[1]), "+f"(d[2]), "+f"(d[3])
                 : "r"(a[0]), "r"(a[1]), "r"(a[2]), "r"(a[3]), "r"(b0), "r"(b1));
}
// pack (c0 -> low bf16, c1 -> high bf16); lo gets the residual pair
__device__ __forceinline__ uint32_t packsplit(float c0, float c1, uint32_t& lo) {
    uint32_t hp;
    asm("cvt.rn.bf16x2.f32 %0, %1, %2;" : "=r"(hp) : "f"(c1), "f"(c0));
    __nv_bfloat162 hb = *reinterpret_cast<__nv_bfloat162*>(&hp);
    float2 hf = __bfloat1622float2(hb);
    uint32_t lp;
    asm("cvt.rn.bf16x2.f32 %0, %1, %2;" : "=r"(lp) : "f"(c1 - hf.y), "f"(c0 - hf.x));
    lo = lp;
    return hp;
}

#define LDB16 72   // bf16 tile stride (64 cols)
#define LDB2  136  // bf16 tile stride (128 cols)
#define LDF32 68   // f32 tile stride (64 cols)
#define LDPF  132  // f32 stage stride (128 cols)

// ==========================================================================
// K0: presplit all f32 operands to bf16 hi/lo. (passing)
// ==========================================================================
__global__ __launch_bounds__(256) void presplit_kernel(
    const float* __restrict__ q, const float* __restrict__ k, const float* __restrict__ v,
    const float* __restrict__ Wq, const float* __restrict__ Wk, const float* __restrict__ Wv,
    const float* __restrict__ Wo)
{
    int blk = blockIdx.x;
    const float* src; __nv_bfloat16 *hi, *lo; int base;
    if      (blk < 1024) { src = q;  hi = iq_hi; lo = iq_lo; base = blk; }
    else if (blk < 2048) { src = k;  hi = ik_hi; lo = ik_lo; base = blk - 1024; }
    else if (blk < 3072) { src = v;  hi = iv_hi; lo = iv_lo; base = blk - 2048; }
    else if (blk < 3328) { src = Wq; hi = wq_hi; lo = wq_lo; base = blk - 3072; }
    else if (blk < 3584) { src = Wk; hi = wk_hi; lo = wk_lo; base = blk - 3328; }
    else if (blk < 3840) { src = Wv; hi = wv_hi; lo = wv_lo; base = blk - 3584; }
    else                 { src = Wo; hi = wo_hi; lo = wo_lo; base = blk - 3840; }

#pragma unroll
    for (int j = 0; j < 4; j++) {
        size_t i4 = (size_t)base * 1024 + j * 256 + threadIdx.x;
        float4 val = ((const float4*)src)[i4];
        __nv_bfloat16 h0,h1,h2,h3,l0,l1,l2,l3;
        split2(val.x, h0, l0); split2(val.y, h1, l1);
        split2(val.z, h2, l2); split2(val.w, h3, l3);
        ((__nv_bfloat162*)hi)[i4*2]   = __halves2bfloat162(h0, h1);
        ((__nv_bfloat162*)hi)[i4*2+1] = __halves2bfloat162(h2, h3);
        ((__nv_bfloat162*)lo)[i4*2]   = __halves2bfloat162(l0, l1);
        ((__nv_bfloat162*)lo)[i4*2+1] = __halves2bfloat162(l2, l3);
    }
}

// ==========================================================================
// K1: fused QKV projection, TWO HEADS per block (tile 128x128).
// grid (32, 24): by -> (pz = by>>3, head-pair = by&7). 256 threads, 2/SM.
// smem: A hi/lo [128][72], B hi/lo [64][136]  = 71680 B.
// ==========================================================================
#define PROJ_SMEM 71680

__global__ __launch_bounds__(256, 2) void proj_kernel()
{
    extern __shared__ char smraw[];
    __nv_bfloat16* sAhi = (__nv_bfloat16*)smraw;             // 128*72
    __nv_bfloat16* sAlo = sAhi + 128 * LDB16;
    __nv_bfloat16* sBhi = sAlo + 128 * LDB16;                // 64*136
    __nv_bfloat16* sBlo = sBhi + 64 * LDB2;

    const int pz = blockIdx.y >> 3;
    const int h0 = (blockIdx.y & 7) * 2;
    const __nv_bfloat16* Xhi = (pz == 0) ? iq_hi : (pz == 1) ? ik_hi : iv_hi;
    const __nv_bfloat16* Xlo = (pz == 0) ? iq_lo : (pz == 1) ? ik_lo : iv_lo;
    const __nv_bfloat16* Whi = ((pz == 0) ? wq_hi : (pz == 1) ? wk_hi : wv_hi) + (size_t)h0 * HID * D_;
    const __nv_bfloat16* Wlo = ((pz == 0) ? wq_lo : (pz == 1) ? wk_lo : wv_lo) + (size_t)h0 * HID * D_;
    __nv_bfloat16* Ohi = (pz == 0) ? pq_hi : (pz == 1) ? pk_hi : pv_hi;
    __nv_bfloat16* Olo = (pz == 0) ? pq_lo : (pz == 1) ? pk_lo : pv_lo;

    const int m0   = blockIdx.x * 128;
    const int tid  = threadIdx.x;
    const int warp = tid >> 5;
    const int wm   = warp & 3;           // 4 row strips of 32
    const int wn   = warp >> 2;          // 2 col strips of 64

    CBf acc[2][4];
#pragma unroll
    for (int i = 0; i < 2; i++)
#pragma unroll
        for (int j = 0; j < 4; j++) wmma::fill_fragment(acc[i][j], 0.0f);

    for (int k0 = 0; k0 < HID; k0 += 64) {
        // A tile: 128 x 64 (hi+lo)
#pragma unroll
        for (int i = tid; i < 1024; i += 256) {
            int r = i >> 3, c8 = (i & 7) * 8;
            size_t g = (size_t)(m0 + r) * HID + k0 + c8;
            *(uint4*)&sAhi[r * LDB16 + c8] = *(const uint4*)&Xhi[g];
            *(uint4*)&sAlo[r * LDB16 + c8] = *(const uint4*)&Xlo[g];
        }
        // B tile: 64 rows x 128 cols (two heads side by side)
#pragma unroll
        for (int i = tid; i < 1024; i += 256) {
            int r = i >> 4, c8 = (i & 15) * 8;
            int head = c8 >> 6, wc = c8 & 63;
            size_t g = (size_t)head * HID * D_ + (size_t)(k0 + r) * D_ + wc;
            *(uint4*)&sBhi[r * LDB2 + c8] = *(const uint4*)&Whi[g];
            *(uint4*)&sBlo[r * LDB2 + c8] = *(const uint4*)&Wlo[g];
        }
        __syncthreads();

#pragma unroll
        for (int kk = 0; kk < 4; kk++) {
            ABf ahi[2], alo[2];
            BBfR bhi[4], blo[4];
#pragma unroll
            for (int i = 0; i < 2; i++) {
                wmma::load_matrix_sync(ahi[i], sAhi + (wm * 32 + i * 16) * LDB16 + kk * 16, LDB16);
                wmma::load_matrix_sync(alo[i], sAlo + (wm * 32 + i * 16) * LDB16 + kk * 16, LDB16);
            }
#pragma unroll
            for (int j = 0; j < 4; j++)
                wmma::load_matrix_sync(bhi[j], sBhi + (kk * 16) * LDB2 + wn * 64 + j * 16, LDB2);
            // term 1
#pragma unroll
            for (int i = 0; i < 2; i++)
#pragma unroll
                for (int j = 0; j < 4; j++)
                    wmma::mma_sync(acc[i][j], ahi[i], bhi[j], acc[i][j]);
#pragma unroll
            for (int j = 0; j < 4; j++)
                wmma::load_matrix_sync(blo[j], sBlo + (kk * 16) * LDB2 + wn * 64 + j * 16, LDB2);
            // term 2
#pragma unroll
            for (int i = 0; i < 2; i++)
#pragma unroll
                for (int j = 0; j < 4; j++)
                    wmma::mma_sync(acc[i][j], ahi[i], blo[j], acc[i][j]);
            // term 3 (bhi still live)
#pragma unroll
            for (int i = 0; i < 2; i++)
#pragma unroll
                for (int j = 0; j < 4; j++)
                    wmma::mma_sync(acc[i][j], alo[i], bhi[j], acc[i][j]);
        }
        __syncthreads();
    }

    // stage 128x128 f32, then split-write both heads
    float* stage = (float*)smraw;                            // 128*132*4 = 67584 B
#pragma unroll
    for (int i = 0; i < 2; i++)
#pragma unroll
        for (int j = 0; j < 4; j++)
            wmma::store_matrix_sync(stage + (size_t)(wm * 32 + i * 16) * LDPF + wn * 64 + j * 16,
                                    acc[i][j], LDPF, wmma::mem_row_major);
    __syncthreads();

    const int b  = m0 >> 11;
    const int s0 = m0 & (S_ - 1);
#pragma unroll
    for (int i = tid; i < 128 * 64; i += 256) {
        int r = i >> 6, c2 = (i & 63) * 2;
        int head = c2 >> 6, wc = c2 & 63;
        float v0 = stage[r * LDPF + c2], v1 = stage[r * LDPF + c2 + 1];
        __nv_bfloat16 hh0,hh1,ll0,ll1;
        split2(v0, hh0, ll0); split2(v1, hh1, ll1);
        size_t g = ((size_t)(b * H_ + h0 + head) * S_ + s0 + r) * D_ + wc;
        *(__nv_bfloat162*)&Ohi[g] = __halves2bfloat162(hh0, hh1);
        *(__nv_bfloat162*)&Olo[g] = __halves2bfloat162(ll0, ll1);
    }
}

// ==========================================================================
// K2: attention, raw mma.sync, register-resident P, term-major (R13, 1068us).
// grid (16, 32), 256 threads (8 warps). Warp w owns q-rows [w*16, w*16+16).
// ==========================================================================
#define ATB 64
#define ANCH (S_/ATB)          // 32
#define KVLD 72
#define AARR (ATB*KVLD)        // 4608 elems per array
#define ABUF (4*AARR)
#define ATTN_SMEM (2*ABUF*2)   // 73728 bytes

__global__ __launch_bounds__(256) void attn_kernel(float* __restrict__ attn_out)
{
    extern __shared__ __nv_bfloat16 skv[];
    const int bh = blockIdx.y, qb = blockIdx.x;
    const int tid = threadIdx.x, w = tid >> 5, lane = tid & 31;
    const int g = lane >> 2, t = lane & 3;
    const size_t qrow0 = (size_t)bh * S_ + (size_t)qb * 128;
    const size_t krow0 = (size_t)bh * S_;
    const int wrow = w * 16;

    uint32_t qh[4][4], ql[4][4];
    {
        const __nv_bfloat16* Qh = pq_hi + (qrow0 + wrow) * D_;
        const __nv_bfloat16* Ql = pq_lo + (qrow0 + wrow) * D_;
#pragma unroll
        for (int ks = 0; ks < 4; ks++) {
            int c0 = ks * 16 + 2 * t;
            qh[ks][0] = *(const uint32_t*)&Qh[(size_t)g * D_ + c0];
            qh[ks][1] = *(const uint32_t*)&Qh[(size_t)(g + 8) * D_ + c0];
            qh[ks][2] = *(const uint32_t*)&Qh[(size_t)g * D_ + c0 + 8];
            qh[ks][3] = *(const uint32_t*)&Qh[(size_t)(g + 8) * D_ + c0 + 8];
            ql[ks][0] = *(const uint32_t*)&Ql[(size_t)g * D_ + c0];
            ql[ks][1] = *(const uint32_t*)&Ql[(size_t)(g + 8) * D_ + c0];
            ql[ks][2] = *(const uint32_t*)&Ql[(size_t)g * D_ + c0 + 8];
            ql[ks][3] = *(const uint32_t*)&Ql[(size_t)(g + 8) * D_ + c0 + 8];
        }
    }

    const int arr = tid >> 6, rr = tid & 63;
    const __nv_bfloat16* mysrc = (arr == 0) ? pk_hi : (arr == 1) ? pk_lo
                               : (arr == 2) ? pv_hi : pv_lo;
    const uint32_t sbase = smem_u32(skv);
    const uint32_t myslot = (uint32_t)((arr * AARR + rr * KVLD) * 2);

    {
        const __nv_bfloat16* src = mysrc + (krow0 + rr) * D_;
        uint32_t dst = sbase + myslot;
#pragma unroll
        for (int s8 = 0; s8 < 8; s8++) cp16(dst + s8 * 16, src + s8 * 8);
        CP_COMMIT();
    }

    const int kr    = (lane & 7) + ((lane & 16) ? 8 : 0);
    const int khalf = ((lane >> 3) & 1) * 8;
    const int vr    = (lane & 7) + (((lane >> 3) & 1) * 8);
    const int vcol  = (lane & 16) ? 8 : 0;

    float accO[8][4];
#pragma unroll
    for (int j = 0; j < 8; j++)
#pragma unroll
        for (int e = 0; e < 4; e++) accO[j][e] = 0.0f;
    float rl = 0.0f, rh = 0.0f;

    for (int ch = 0; ch < ANCH; ch++) {
        __syncthreads();
        if (ch + 1 < ANCH) {
            const __nv_bfloat16* src = mysrc + (krow0 + (size_t)(ch + 1) * ATB + rr) * D_;
            uint32_t dst = sbase + (uint32_t)(((ch + 1) & 1) * ABUF * 2) + myslot;
#pragma unroll
            for (int s8 = 0; s8 < 8; s8++) cp16(dst + s8 * 16, src + s8 * 8);
            CP_COMMIT();
            CP_WAIT1();
        } else {
            CP_WAIT0();
        }
        __syncthreads();

        const uint32_t bufb = sbase + (uint32_t)((ch & 1) * ABUF * 2);
        const uint32_t kHiB = bufb;
        const uint32_t kLoB = bufb + AARR * 2;
        const uint32_t vHiB = bufb + 2 * AARR * 2;
        const uint32_t vLoB = bufb + 3 * AARR * 2;

        float accS[8][4];
#pragma unroll
        for (int j = 0; j < 8; j++)
#pragma unroll
            for (int e = 0; e < 4; e++) accS[j][e] = 0.0f;

#pragma unroll
        for (int ks = 0; ks < 4; ks++) {
            uint32_t kh[4][4], kl[4][4];
#pragma unroll
            for (int j = 0; j < 4; j++) {
                uint32_t koff = (uint32_t)(((16 * j + kr) * KVLD + ks * 16 + khalf) * 2);
                ldsm4(kh[j][0], kh[j][1], kh[j][2], kh[j][3], kHiB + koff);
                ldsm4(kl[j][0], kl[j][1], kl[j][2], kl[j][3], kLoB + koff);
            }
#pragma unroll
            for (int j = 0; j < 4; j++) {
                mma16816(accS[2 * j],     qh[ks], kh[j][0], kh[j][1]);
                mma16816(accS[2 * j + 1], qh[ks], kh[j][2], kh[j][3]);
            }
#pragma unroll
            for (int j = 0; j < 4; j++) {
                mma16816(accS[2 * j],     qh[ks], kl[j][0], kl[j][1]);
                mma16816(accS[2 * j + 1], qh[ks], kl[j][2], kl[j][3]);
            }
#pragma unroll
            for (int j = 0; j < 4; j++) {
                mma16816(accS[2 * j],     ql[ks], kh[j][0], kh[j][1]);
                mma16816(accS[2 * j + 1], ql[ks], kh[j][2], kh[j][3]);
            }
        }

#pragma unroll
        for (int j = 0; j < 8; j++) {
            float e0 = __expf(accS[j][0] * 0.125f);
            float e1 = __expf(accS[j][1] * 0.125f);
            float e2 = __expf(accS[j][2] * 0.125f);
            float e3 = __expf(accS[j][3] * 0.125f);
            accS[j][0] = e0; accS[j][1] = e1; accS[j][2] = e2; accS[j][3] = e3;
            rl += e0 + e1;
            rh += e2 + e3;
            if (attn_out) {
                size_t col = (size_t)ch * ATB + j * 8 + 2 * t;
                *(float2*)&attn_out[(qrow0 + wrow + g) * S_ + col]     = make_float2(e0, e1);
                *(float2*)&attn_out[(qrow0 + wrow + 8 + g) * S_ + col] = make_float2(e2, e3);
            }
        }

#pragma unroll
        for (int ks = 0; ks < 4; ks++) {
            uint32_t pah[4], pal[4];
            pah[0] = packsplit(accS[2 * ks][0],     accS[2 * ks][1],     pal[0]);
            pah[1] = packsplit(accS[2 * ks][2],     accS[2 * ks][3],     pal[1]);
            pah[2] = packsplit(accS[2 * ks + 1][0], accS[2 * ks + 1][1], pal[2]);
            pah[3] = packsplit(accS[2 * ks + 1][2], accS[2 * ks + 1][3], pal[3]);
            uint32_t vh[4][4], vl[4][4];
#pragma unroll
            for (int j = 0; j < 4; j++) {
                uint32_t voff = (uint32_t)(((ks * 16 + vr) * KVLD + 16 * j + vcol) * 2);
                ldsm4t(vh[j][0], vh[j][1], vh[j][2], vh[j][3], vHiB + voff);
                ldsm4t(vl[j][0], vl[j][1], vl[j][2], vl[j][3], vLoB + voff);
            }
#pragma unroll
            for (int j = 0; j < 4; j++) {
                mma16816(accO[2 * j],     pah, vh[j][0], vh[j][1]);
                mma16816(accO[2 * j + 1], pah, vh[j][2], vh[j][3]);
            }
#pragma unroll
            for (int j = 0; j < 4; j++) {
                mma16816(accO[2 * j],     pah, vl[j][0], vl[j][1]);
                mma16816(accO[2 * j + 1], pah, vl[j][2], vl[j][3]);
            }
#pragma unroll
            for (int j = 0; j < 4; j++) {
                mma16816(accO[2 * j],     pal, vh[j][0], vh[j][1]);
                mma16816(accO[2 * j + 1], pal, vh[j][2], vh[j][3]);
            }
        }
    }

    rl += __shfl_xor_sync(0xffffffffu, rl, 1);
    rl += __shfl_xor_sync(0xffffffffu, rl, 2);
    rh += __shfl_xor_sync(0xffffffffu, rh, 1);
    rh += __shfl_xor_sync(0xffffffffu, rh, 2);
    const float invl = 1.0f / rl, invh = 1.0f / rh;
    if (t == 0) {
        g_invsum[qrow0 + wrow + g]     = invl;
        g_invsum[qrow0 + wrow + 8 + g] = invh;
    }

    const int b = bh >> 4, h = bh & 15;
    const size_t rowg = (size_t)b * S_ + (size_t)qb * 128 + wrow + g;
#pragma unroll
    for (int j = 0; j < 8; j++) {
        int col = h * D_ + j * 8 + 2 * t;
        float o0 = accO[j][0] * invl, o1 = accO[j][1] * invl;
        float o2 = accO[j][2] * invh, o3 = accO[j][3] * invh;
        __nv_bfloat16 h0, h1, l0, l1;
        split2(o0, h0, l0); split2(o1, h1, l1);
        *(__nv_bfloat162*)&cat_hi[rowg * HID + col] = __halves2bfloat162(h0, h1);
        *(__nv_bfloat162*)&cat_lo[rowg * HID + col] = __halves2bfloat162(l0, l1);
        split2(o2, h0, l0); split2(o3, h1, l1);
        *(__nv_bfloat162*)&cat_hi[(rowg + 8) * HID + col] = __halves2bfloat162(h0, h1);
        *(__nv_bfloat162*)&cat_lo[(rowg + 8) * HID + col] = __halves2bfloat162(l0, l1);
    }
}

// ==========================================================================
// K3: FUSED out-projection + attn normalization, 1:2 interleave.
// grid 1536: bx%3==2 -> GEMM block (512, tile 128x64);
//            bx%3 in {0,1} -> scale block (1024, 64 attn rows, MLP=8).
// ==========================================================================
__global__ __launch_bounds__(256, 2) void outproj_scale_kernel(
    float* __restrict__ out, float* __restrict__ attn_out)
{
    const int bx  = blockIdx.x;
    const int tid = threadIdx.x;

    if ((bx % 3) != 2) {
        // ---- scale branch: 64 rows of attn per block, 8-wide MLP ----
        if (!attn_out) return;
        const int sidx = (bx / 3) * 2 + (bx % 3);
        const size_t row0 = (size_t)sidx * 64;
        float4* p = (float4*)(attn_out + row0 * S_);
        // 64 rows * 512 float4 = 32768; 256 threads, 8 independent per iter
        for (int i0 = tid; i0 < 32768; i0 += 2048) {
            float4 v[8];
#pragma unroll
            for (int k = 0; k < 8; k++) v[k] = p[i0 + k * 256];
#pragma unroll
            for (int k = 0; k < 8; k++) {
                int i = i0 + k * 256;
                float inv = g_invsum[row0 + (i >> 9)];
                v[k].x *= inv; v[k].y *= inv; v[k].z *= inv; v[k].w *= inv;
                p[i] = v[k];
            }
        }
        return;
    }

    // ---- outproj branch ----
    const int idx = bx / 3;
    extern __shared__ char smraw[];
    __nv_bfloat16* sAhi = (__nv_bfloat16*)smraw;
    __nv_bfloat16* sAlo = sAhi + 128 * LDB16;
    __nv_bfloat16* sBhi = sAlo + 128 * LDB16;
    __nv_bfloat16* sBlo = sBhi + 64 * LDB16;

    const int m0 = (idx & 31) * 128;
    const int n0 = (idx >> 5) * 64;
    const int warp = tid >> 5;
    const int wm = warp & 3;
    const int wn = warp >> 2;

    CBf acc[2][2];
#pragma unroll
    for (int i = 0; i < 2; i++)
#pragma unroll
        for (int j = 0; j < 2; j++) wmma::fill_fragment(acc[i][j], 0.0f);

    for (int k0 = 0; k0 < HID; k0 += 64) {
#pragma unroll
        for (int i = tid; i < 1024; i += 256) {
            int r = i >> 3, c8 = (i & 7) * 8;
            size_t g = (size_t)(m0 + r) * HID + k0 + c8;
            *(uint4*)&sAhi[r * LDB16 + c8] = *(const uint4*)&cat_hi[g];
            *(uint4*)&sAlo[r * LDB16 + c8] = *(const uint4*)&cat_lo[g];
        }
#pragma unroll
        for (int i = tid; i < 512; i += 256) {
            int r = i >> 3, c8 = (i & 7) * 8;
            size_t g = (size_t)(k0 + r) * HID + n0 + c8;
            *(uint4*)&sBhi[r * LDB16 + c8] = *(const uint4*)&wo_hi[g];
            *(uint4*)&sBlo[r * LDB16 + c8] = *(const uint4*)&wo_lo[g];
        }
        __syncthreads();

#pragma unroll
        for (int kk = 0; kk < 4; kk++) {
            ABf ahi[2], alo[2];
            BBfR bhi[2], blo[2];
#pragma unroll
            for (int i = 0; i < 2; i++) {
                wmma::load_matrix_sync(ahi[i], sAhi + (wm * 32 + i * 16) * LDB16 + kk * 16, LDB16);
                wmma::load_matrix_sync(alo[i], sAlo + (wm * 32 + i * 16) * LDB16 + kk * 16, LDB16);
            }
#pragma unroll
            for (int j = 0; j < 2; j++) {
                wmma::load_matrix_sync(bhi[j], sBhi + (kk * 16) * LDB16 + wn * 32 + j * 16, LDB16);
                wmma::load_matrix_sync(blo[j], sBlo + (kk * 16) * LDB16 + wn * 32 + j * 16, LDB16);
            }
#pragma unroll
            for (int i = 0; i < 2; i++)
#pragma unroll
                for (int j = 0; j < 2; j++)
                    wmma::mma_sync(acc[i][j], ahi[i], bhi[j], acc[i][j]);
#pragma unroll
            for (int i = 0; i < 2; i++)
#pragma unroll
                for (int j = 0; j < 2; j++)
                    wmma::mma_sync(acc[i][j], ahi[i], blo[j], acc[i][j]);
#pragma unroll
            for (int i = 0; i < 2; i++)
#pragma unroll
                for (int j = 0; j < 2; j++)
                    wmma::mma_sync(acc[i][j], alo[i], bhi[j], acc[i][j]);
        }
        __syncthreads();
    }

    float* obase = out + (size_t)m0 * HID + n0;
#pragma unroll
    for (int i = 0; i < 2; i++)
#pragma unroll
        for (int j = 0; j < 2; j++)
            wmma::store_matrix_sync(obase + (size_t)(wm * 32 + i * 16) * HID + wn * 32 + j * 16,
                                    acc[i][j], HID, wmma::mem_row_major);
}

// ==========================================================================
extern "C" void kernel_launch(void* const* d_in, const int* in_sizes, int n_in,
                              void* d_out, int out_size)
{
    const float* q  = (const float*)d_in[0];
    const float* k  = (const float*)d_in[1];
    const float* v  = (const float*)d_in[2];
    const float* Wq = (const float*)d_in[3];
    const float* Wk = (const float*)d_in[4];
    const float* Wv = (const float*)d_in[5];
    const float* Wo = (const float*)d_in[6];

    float* out  = (float*)d_out;
    float* attn = nullptr;
    const long long OUT_ELEMS  = (long long)MROWS * HID;
    const long long ATTN_ELEMS = (long long)B_ * H_ * S_ * S_;
    if ((long long)out_size >= OUT_ELEMS + ATTN_ELEMS)
        attn = out + OUT_ELEMS;

    const int gemm_smem = (128 + 64) * LDB16 * 2 * 2;        // 55296 bytes
    cudaFuncSetAttribute(proj_kernel,          cudaFuncAttributeMaxDynamicSharedMemorySize, PROJ_SMEM);
    cudaFuncSetAttribute(outproj_scale_kernel, cudaFuncAttributeMaxDynamicSharedMemorySize, gemm_smem);
    cudaFuncSetAttribute(attn_kernel,          cudaFuncAttributeMaxDynamicSharedMemorySize, ATTN_SMEM);

    presplit_kernel<<<4096, 256>>>(q, k, v, Wq, Wk, Wv, Wo);

    dim3 g1(MROWS / 128, 3 * 8);
    proj_kernel<<<g1, 256, PROJ_SMEM>>>();

    dim3 g2(S_ / 128, B_ * H_);
    attn_kernel<<<g2, 256, ATTN_SMEM>>>(attn);

    outproj_scale_kernel<<<1536, 256, gemm_smem>>>(out, attn);
}

// round 17
// speedup vs baseline: 1.0575x; 1.0575x over previous
#include <cuda_runtime.h>
#include <cuda_bf16.h>
#include <mma.h>
#include <cstdint>
#include <cstddef>

using namespace nvcuda;

#define B_   2
#define S_   2048
#define H_   16
#define D_   64
#define HID  1024
#define MROWS (B_*S_)          // 4096
#define XN (MROWS*HID)         // 4,194,304
#define WN (H_*HID*D_)         // 1,048,576

// ---------------- global scratch (static; no allocations) -----------------
__device__ __nv_bfloat16 iq_hi[XN], iq_lo[XN], ik_hi[XN], ik_lo[XN], iv_hi[XN], iv_lo[XN];
__device__ __nv_bfloat16 wq_hi[WN], wq_lo[WN], wk_hi[WN], wk_lo[WN], wv_hi[WN], wv_lo[WN];
__device__ __nv_bfloat16 wo_hi[WN], wo_lo[WN];
__device__ __nv_bfloat16 pq_hi[XN], pq_lo[XN], pk_hi[XN], pk_lo[XN], pv_hi[XN], pv_lo[XN];
__device__ __nv_bfloat16 cat_hi[XN], cat_lo[XN];

// ---------------- wmma fragment types (proj / outproj) --------------------
typedef wmma::fragment<wmma::matrix_a, 16, 16, 16, __nv_bfloat16, wmma::row_major> ABf;
typedef wmma::fragment<wmma::matrix_b, 16, 16, 16, __nv_bfloat16, wmma::row_major> BBfR;
typedef wmma::fragment<wmma::accumulator, 16, 16, 16, float> CBf;

__device__ __forceinline__ void split2(float x, __nv_bfloat16& hi, __nv_bfloat16& lo) {
    hi = __float2bfloat16(x);
    lo = __float2bfloat16(x - __bfloat162float(hi));
}

// ---------------- cp.async helpers ----------------------------------------
__device__ __forceinline__ void cp16(uint32_t saddr, const void* gaddr) {
    asm volatile("cp.async.cg.shared.global [%0], [%1], 16;\n" :: "r"(saddr), "l"(gaddr));
}
#define CP_COMMIT() asm volatile("cp.async.commit_group;\n" ::: "memory")
#define CP_WAIT1()  asm volatile("cp.async.wait_group 1;\n" ::: "memory")
#define CP_WAIT0()  asm volatile("cp.async.wait_group 0;\n" ::: "memory")

__device__ __forceinline__ uint32_t smem_u32(const void* p) {
    uint32_t a;
    asm("{ .reg .u64 t; cvta.to.shared.u64 t, %1; cvt.u32.u64 %0, t; }" : "=r"(a) : "l"(p));
    return a;
}

// ---------------- raw mma helpers (attn) -----------------------------------
__device__ __forceinline__ void ldsm4(uint32_t& r0, uint32_t& r1, uint32_t& r2, uint32_t& r3, uint32_t a) {
    asm volatile("ldmatrix.sync.aligned.m8n8.x4.shared.b16 {%0,%1,%2,%3}, [%4];"
                 : "=r"(r0), "=r"(r1), "=r"(r2), "=r"(r3) : "r"(a));
}
__device__ __forceinline__ void ldsm4t(uint32_t& r0, uint32_t& r1, uint32_t& r2, uint32_t& r3, uint32_t a) {
    asm volatile("ldmatrix.sync.aligned.m8n8.x4.trans.shared.b16 {%0,%1,%2,%3}, [%4];"
                 : "=r"(r0), "=r"(r1), "=r"(r2), "=r"(r3) : "r"(a));
}
__device__ __forceinline__ void mma16816(float* d, const uint32_t* a, uint32_t b0, uint32_t b1) {
    asm volatile("mma.sync.aligned.m16n8k16.row.col.f32.bf16.bf16.f32 "
                 "{%0,%1,%2,%3}, {%4,%5,%6,%7}, {%8,%9}, {%0,%1,%2,%3};"
                 : "+f"(d[0]), "+f"(d[1]), "+f"(d[2]), "+f"(d[3])
                 : "r"(a[0]), "r"(a[1]), "r"(a[2]), "r"(a[3]), "r"(b0), "r"(b1));
}
// pack (c0 -> low bf16, c1 -> high bf16); lo gets the residual pair
__device__ __forceinline__ uint32_t packsplit(float c0, float c1, uint32_t& lo) {
    uint32_t hp;
    asm("cvt.rn.bf16x2.f32 %0, %1, %2;" : "=r"(hp) : "f"(c1), "f"(c0));
    __nv_bfloat162 hb = *reinterpret_cast<__nv_bfloat162*>(&hp);
    float2 hf = __bfloat1622float2(hb);
    uint32_t lp;
    asm("cvt.rn.bf16x2.f32 %0, %1, %2;" : "=r"(lp) : "f"(c1 - hf.y), "f"(c0 - hf.x));
    lo = lp;
    return hp;
}

#define LDB16 72   // bf16 tile stride (64 cols)
#define LDB2  136  // bf16 tile stride (128 cols)
#define LDF32 68   // f32 tile stride (64 cols)
#define LDPF  132  // f32 stage stride (128 cols)

// ==========================================================================
// K0: presplit all f32 operands to bf16 hi/lo. (passing)
// ==========================================================================
__global__ __launch_bounds__(256) void presplit_kernel(
    const float* __restrict__ q, const float* __restrict__ k, const float* __restrict__ v,
    const float* __restrict__ Wq, const float* __restrict__ Wk, const float* __restrict__ Wv,
    const float* __restrict__ Wo)
{
    int blk = blockIdx.x;
    const float* src; __nv_bfloat16 *hi, *lo; int base;
    if      (blk < 1024) { src = q;  hi = iq_hi; lo = iq_lo; base = blk; }
    else if (blk < 2048) { src = k;  hi = ik_hi; lo = ik_lo; base = blk - 1024; }
    else if (blk < 3072) { src = v;  hi = iv_hi; lo = iv_lo; base = blk - 2048; }
    else if (blk < 3328) { src = Wq; hi = wq_hi; lo = wq_lo; base = blk - 3072; }
    else if (blk < 3584) { src = Wk; hi = wk_hi; lo = wk_lo; base = blk - 3328; }
    else if (blk < 3840) { src = Wv; hi = wv_hi; lo = wv_lo; base = blk - 3584; }
    else                 { src = Wo; hi = wo_hi; lo = wo_lo; base = blk - 3840; }

#pragma unroll
    for (int j = 0; j < 4; j++) {
        size_t i4 = (size_t)base * 1024 + j * 256 + threadIdx.x;
        float4 val = ((const float4*)src)[i4];
        __nv_bfloat16 h0,h1,h2,h3,l0,l1,l2,l3;
        split2(val.x, h0, l0); split2(val.y, h1, l1);
        split2(val.z, h2, l2); split2(val.w, h3, l3);
        ((__nv_bfloat162*)hi)[i4*2]   = __halves2bfloat162(h0, h1);
        ((__nv_bfloat162*)hi)[i4*2+1] = __halves2bfloat162(h2, h3);
        ((__nv_bfloat162*)lo)[i4*2]   = __halves2bfloat162(l0, l1);
        ((__nv_bfloat162*)lo)[i4*2+1] = __halves2bfloat162(l2, l3);
    }
}

// ==========================================================================
// K1: fused QKV projection, TWO HEADS per block (tile 128x128). (R16, kept)
// grid (32, 24). 256 threads, 2/SM.
// ==========================================================================
#define PROJ_SMEM 71680

__global__ __launch_bounds__(256, 2) void proj_kernel()
{
    extern __shared__ char smraw[];
    __nv_bfloat16* sAhi = (__nv_bfloat16*)smraw;             // 128*72
    __nv_bfloat16* sAlo = sAhi + 128 * LDB16;
    __nv_bfloat16* sBhi = sAlo + 128 * LDB16;                // 64*136
    __nv_bfloat16* sBlo = sBhi + 64 * LDB2;

    const int pz = blockIdx.y >> 3;
    const int h0 = (blockIdx.y & 7) * 2;
    const __nv_bfloat16* Xhi = (pz == 0) ? iq_hi : (pz == 1) ? ik_hi : iv_hi;
    const __nv_bfloat16* Xlo = (pz == 0) ? iq_lo : (pz == 1) ? ik_lo : iv_lo;
    const __nv_bfloat16* Whi = ((pz == 0) ? wq_hi : (pz == 1) ? wk_hi : wv_hi) + (size_t)h0 * HID * D_;
    const __nv_bfloat16* Wlo = ((pz == 0) ? wq_lo : (pz == 1) ? wk_lo : wv_lo) + (size_t)h0 * HID * D_;
    __nv_bfloat16* Ohi = (pz == 0) ? pq_hi : (pz == 1) ? pk_hi : pv_hi;
    __nv_bfloat16* Olo = (pz == 0) ? pq_lo : (pz == 1) ? pk_lo : pv_lo;

    const int m0   = blockIdx.x * 128;
    const int tid  = threadIdx.x;
    const int warp = tid >> 5;
    const int wm   = warp & 3;
    const int wn   = warp >> 2;

    CBf acc[2][4];
#pragma unroll
    for (int i = 0; i < 2; i++)
#pragma unroll
        for (int j = 0; j < 4; j++) wmma::fill_fragment(acc[i][j], 0.0f);

    for (int k0 = 0; k0 < HID; k0 += 64) {
#pragma unroll
        for (int i = tid; i < 1024; i += 256) {
            int r = i >> 3, c8 = (i & 7) * 8;
            size_t g = (size_t)(m0 + r) * HID + k0 + c8;
            *(uint4*)&sAhi[r * LDB16 + c8] = *(const uint4*)&Xhi[g];
            *(uint4*)&sAlo[r * LDB16 + c8] = *(const uint4*)&Xlo[g];
        }
#pragma unroll
        for (int i = tid; i < 1024; i += 256) {
            int r = i >> 4, c8 = (i & 15) * 8;
            int head = c8 >> 6, wc = c8 & 63;
            size_t g = (size_t)head * HID * D_ + (size_t)(k0 + r) * D_ + wc;
            *(uint4*)&sBhi[r * LDB2 + c8] = *(const uint4*)&Whi[g];
            *(uint4*)&sBlo[r * LDB2 + c8] = *(const uint4*)&Wlo[g];
        }
        __syncthreads();

#pragma unroll
        for (int kk = 0; kk < 4; kk++) {
            ABf ahi[2], alo[2];
            BBfR bhi[4], blo[4];
#pragma unroll
            for (int i = 0; i < 2; i++) {
                wmma::load_matrix_sync(ahi[i], sAhi + (wm * 32 + i * 16) * LDB16 + kk * 16, LDB16);
                wmma::load_matrix_sync(alo[i], sAlo + (wm * 32 + i * 16) * LDB16 + kk * 16, LDB16);
            }
#pragma unroll
            for (int j = 0; j < 4; j++)
                wmma::load_matrix_sync(bhi[j], sBhi + (kk * 16) * LDB2 + wn * 64 + j * 16, LDB2);
#pragma unroll
            for (int i = 0; i < 2; i++)
#pragma unroll
                for (int j = 0; j < 4; j++)
                    wmma::mma_sync(acc[i][j], ahi[i], bhi[j], acc[i][j]);
#pragma unroll
            for (int j = 0; j < 4; j++)
                wmma::load_matrix_sync(blo[j], sBlo + (kk * 16) * LDB2 + wn * 64 + j * 16, LDB2);
#pragma unroll
            for (int i = 0; i < 2; i++)
#pragma unroll
                for (int j = 0; j < 4; j++)
                    wmma::mma_sync(acc[i][j], ahi[i], blo[j], acc[i][j]);
#pragma unroll
            for (int i = 0; i < 2; i++)
#pragma unroll
                for (int j = 0; j < 4; j++)
                    wmma::mma_sync(acc[i][j], alo[i], bhi[j], acc[i][j]);
        }
        __syncthreads();
    }

    float* stage = (float*)smraw;                            // 128*132*4 = 67584 B
#pragma unroll
    for (int i = 0; i < 2; i++)
#pragma unroll
        for (int j = 0; j < 4; j++)
            wmma::store_matrix_sync(stage + (size_t)(wm * 32 + i * 16) * LDPF + wn * 64 + j * 16,
                                    acc[i][j], LDPF, wmma::mem_row_major);
    __syncthreads();

    const int b  = m0 >> 11;
    const int s0 = m0 & (S_ - 1);
#pragma unroll
    for (int i = tid; i < 128 * 64; i += 256) {
        int r = i >> 6, c2 = (i & 63) * 2;
        int head = c2 >> 6, wc = c2 & 63;
        float v0 = stage[r * LDPF + c2], v1 = stage[r * LDPF + c2 + 1];
        __nv_bfloat16 hh0,hh1,ll0,ll1;
        split2(v0, hh0, ll0); split2(v1, hh1, ll1);
        size_t g = ((size_t)(b * H_ + h0 + head) * S_ + s0 + r) * D_ + wc;
        *(__nv_bfloat162*)&Ohi[g] = __halves2bfloat162(hh0, hh1);
        *(__nv_bfloat162*)&Olo[g] = __halves2bfloat162(ll0, ll1);
    }
}

// ==========================================================================
// K2: attention (R13 core) + IN-KERNEL attn normalization epilogue.
// grid (16, 32), 256 threads (8 warps). Warp w owns q-rows [w*16, w*16+16).
// After the chunk loop: broadcast 128 inv-sums via smem, then each block
// rescales its own 128 x 2048 slice of attn_out (recent chunks L2-hot).
// ==========================================================================
#define ATB 64
#define ANCH (S_/ATB)          // 32
#define KVLD 72
#define AARR (ATB*KVLD)        // 4608 elems per array
#define ABUF (4*AARR)
#define ATTN_SMEM (2*ABUF*2)   // 73728 bytes

__global__ __launch_bounds__(256) void attn_kernel(float* __restrict__ attn_out)
{
    extern __shared__ __nv_bfloat16 skv[];
    const int bh = blockIdx.y, qb = blockIdx.x;
    const int tid = threadIdx.x, w = tid >> 5, lane = tid & 31;
    const int g = lane >> 2, t = lane & 3;
    const size_t qrow0 = (size_t)bh * S_ + (size_t)qb * 128;
    const size_t krow0 = (size_t)bh * S_;
    const int wrow = w * 16;

    uint32_t qh[4][4], ql[4][4];
    {
        const __nv_bfloat16* Qh = pq_hi + (qrow0 + wrow) * D_;
        const __nv_bfloat16* Ql = pq_lo + (qrow0 + wrow) * D_;
#pragma unroll
        for (int ks = 0; ks < 4; ks++) {
            int c0 = ks * 16 + 2 * t;
            qh[ks][0] = *(const uint32_t*)&Qh[(size_t)g * D_ + c0];
            qh[ks][1] = *(const uint32_t*)&Qh[(size_t)(g + 8) * D_ + c0];
            qh[ks][2] = *(const uint32_t*)&Qh[(size_t)g * D_ + c0 + 8];
            qh[ks][3] = *(const uint32_t*)&Qh[(size_t)(g + 8) * D_ + c0 + 8];
            ql[ks][0] = *(const uint32_t*)&Ql[(size_t)g * D_ + c0];
            ql[ks][1] = *(const uint32_t*)&Ql[(size_t)(g + 8) * D_ + c0];
            ql[ks][2] = *(const uint32_t*)&Ql[(size_t)g * D_ + c0 + 8];
            ql[ks][3] = *(const uint32_t*)&Ql[(size_t)(g + 8) * D_ + c0 + 8];
        }
    }

    const int arr = tid >> 6, rr = tid & 63;
    const __nv_bfloat16* mysrc = (arr == 0) ? pk_hi : (arr == 1) ? pk_lo
                               : (arr == 2) ? pv_hi : pv_lo;
    const uint32_t sbase = smem_u32(skv);
    const uint32_t myslot = (uint32_t)((arr * AARR + rr * KVLD) * 2);

    {
        const __nv_bfloat16* src = mysrc + (krow0 + rr) * D_;
        uint32_t dst = sbase + myslot;
#pragma unroll
        for (int s8 = 0; s8 < 8; s8++) cp16(dst + s8 * 16, src + s8 * 8);
        CP_COMMIT();
    }

    const int kr    = (lane & 7) + ((lane & 16) ? 8 : 0);
    const int khalf = ((lane >> 3) & 1) * 8;
    const int vr    = (lane & 7) + (((lane >> 3) & 1) * 8);
    const int vcol  = (lane & 16) ? 8 : 0;

    float accO[8][4];
#pragma unroll
    for (int j = 0; j < 8; j++)
#pragma unroll
        for (int e = 0; e < 4; e++) accO[j][e] = 0.0f;
    float rl = 0.0f, rh = 0.0f;

    for (int ch = 0; ch < ANCH; ch++) {
        __syncthreads();
        if (ch + 1 < ANCH) {
            const __nv_bfloat16* src = mysrc + (krow0 + (size_t)(ch + 1) * ATB + rr) * D_;
            uint32_t dst = sbase + (uint32_t)(((ch + 1) & 1) * ABUF * 2) + myslot;
#pragma unroll
            for (int s8 = 0; s8 < 8; s8++) cp16(dst + s8 * 16, src + s8 * 8);
            CP_COMMIT();
            CP_WAIT1();
        } else {
            CP_WAIT0();
        }
        __syncthreads();

        const uint32_t bufb = sbase + (uint32_t)((ch & 1) * ABUF * 2);
        const uint32_t kHiB = bufb;
        const uint32_t kLoB = bufb + AARR * 2;
        const uint32_t vHiB = bufb + 2 * AARR * 2;
        const uint32_t vLoB = bufb + 3 * AARR * 2;

        float accS[8][4];
#pragma unroll
        for (int j = 0; j < 8; j++)
#pragma unroll
            for (int e = 0; e < 4; e++) accS[j][e] = 0.0f;

#pragma unroll
        for (int ks = 0; ks < 4; ks++) {
            uint32_t kh[4][4], kl[4][4];
#pragma unroll
            for (int j = 0; j < 4; j++) {
                uint32_t koff = (uint32_t)(((16 * j + kr) * KVLD + ks * 16 + khalf) * 2);
                ldsm4(kh[j][0], kh[j][1], kh[j][2], kh[j][3], kHiB + koff);
                ldsm4(kl[j][0], kl[j][1], kl[j][2], kl[j][3], kLoB + koff);
            }
#pragma unroll
            for (int j = 0; j < 4; j++) {
                mma16816(accS[2 * j],     qh[ks], kh[j][0], kh[j][1]);
                mma16816(accS[2 * j + 1], qh[ks], kh[j][2], kh[j][3]);
            }
#pragma unroll
            for (int j = 0; j < 4; j++) {
                mma16816(accS[2 * j],     qh[ks], kl[j][0], kl[j][1]);
                mma16816(accS[2 * j + 1], qh[ks], kl[j][2], kl[j][3]);
            }
#pragma unroll
            for (int j = 0; j < 4; j++) {
                mma16816(accS[2 * j],     ql[ks], kh[j][0], kh[j][1]);
                mma16816(accS[2 * j + 1], ql[ks], kh[j][2], kh[j][3]);
            }
        }

#pragma unroll
        for (int j = 0; j < 8; j++) {
            float e0 = __expf(accS[j][0] * 0.125f);
            float e1 = __expf(accS[j][1] * 0.125f);
            float e2 = __expf(accS[j][2] * 0.125f);
            float e3 = __expf(accS[j][3] * 0.125f);
            accS[j][0] = e0; accS[j][1] = e1; accS[j][2] = e2; accS[j][3] = e3;
            rl += e0 + e1;
            rh += e2 + e3;
            if (attn_out) {
                size_t col = (size_t)ch * ATB + j * 8 + 2 * t;
                *(float2*)&attn_out[(qrow0 + wrow + g) * S_ + col]     = make_float2(e0, e1);
                *(float2*)&attn_out[(qrow0 + wrow + 8 + g) * S_ + col] = make_float2(e2, e3);
            }
        }

#pragma unroll
        for (int ks = 0; ks < 4; ks++) {
            uint32_t pah[4], pal[4];
            pah[0] = packsplit(accS[2 * ks][0],     accS[2 * ks][1],     pal[0]);
            pah[1] = packsplit(accS[2 * ks][2],     accS[2 * ks][3],     pal[1]);
            pah[2] = packsplit(accS[2 * ks + 1][0], accS[2 * ks + 1][1], pal[2]);
            pah[3] = packsplit(accS[2 * ks + 1][2], accS[2 * ks + 1][3], pal[3]);
            uint32_t vh[4][4], vl[4][4];
#pragma unroll
            for (int j = 0; j < 4; j++) {
                uint32_t voff = (uint32_t)(((ks * 16 + vr) * KVLD + 16 * j + vcol) * 2);
                ldsm4t(vh[j][0], vh[j][1], vh[j][2], vh[j][3], vHiB + voff);
                ldsm4t(vl[j][0], vl[j][1], vl[j][2], vl[j][3], vLoB + voff);
            }
#pragma unroll
            for (int j = 0; j < 4; j++) {
                mma16816(accO[2 * j],     pah, vh[j][0], vh[j][1]);
                mma16816(accO[2 * j + 1], pah, vh[j][2], vh[j][3]);
            }
#pragma unroll
            for (int j = 0; j < 4; j++) {
                mma16816(accO[2 * j],     pah, vl[j][0], vl[j][1]);
                mma16816(accO[2 * j + 1], pah, vl[j][2], vl[j][3]);
            }
#pragma unroll
            for (int j = 0; j < 4; j++) {
                mma16816(accO[2 * j],     pal, vh[j][0], vh[j][1]);
                mma16816(accO[2 * j + 1], pal, vh[j][2], vh[j][3]);
            }
        }
    }

    // ---- rowsum reduce across t lanes ----
    rl += __shfl_xor_sync(0xffffffffu, rl, 1);
    rl += __shfl_xor_sync(0xffffffffu, rl, 2);
    rh += __shfl_xor_sync(0xffffffffu, rh, 1);
    rh += __shfl_xor_sync(0xffffffffu, rh, 2);
    const float invl = 1.0f / rl, invh = 1.0f / rh;

    // ---- broadcast 128 inv-sums through smem (buffer-0 region is idle:
    //      last chunk ch=31 uses buffer 1) ----
    float* sInv = (float*)skv;
    if (t == 0) {
        sInv[wrow + g]     = invl;
        sInv[wrow + 8 + g] = invh;
    }
    __syncthreads();

    // ---- normalize this block's own attn rows (128 x 2048) ----
    if (attn_out) {
        float4* pbase = (float4*)(attn_out + qrow0 * S_);
#pragma unroll 4
        for (int i = tid; i < 128 * (S_ / 4); i += 256) {
            float inv = sInv[i >> 9];
            float4 v = pbase[i];
            v.x *= inv; v.y *= inv; v.z *= inv; v.w *= inv;
            pbase[i] = v;
        }
    }

    // ---- O epilogue ----
    const int b = bh >> 4, h = bh & 15;
    const size_t rowg = (size_t)b * S_ + (size_t)qb * 128 + wrow + g;
#pragma unroll
    for (int j = 0; j < 8; j++) {
        int col = h * D_ + j * 8 + 2 * t;
        float o0 = accO[j][0] * invl, o1 = accO[j][1] * invl;
        float o2 = accO[j][2] * invh, o3 = accO[j][3] * invh;
        __nv_bfloat16 h0, h1, l0, l1;
        split2(o0, h0, l0); split2(o1, h1, l1);
        *(__nv_bfloat162*)&cat_hi[rowg * HID + col] = __halves2bfloat162(h0, h1);
        *(__nv_bfloat162*)&cat_lo[rowg * HID + col] = __halves2bfloat162(l0, l1);
        split2(o2, h0, l0); split2(o3, h1, l1);
        *(__nv_bfloat162*)&cat_hi[(rowg + 8) * HID + col] = __halves2bfloat162(h0, h1);
        *(__nv_bfloat162*)&cat_lo[(rowg + 8) * HID + col] = __halves2bfloat162(l0, l1);
    }
}

// ==========================================================================
// K3: out-projection GEMM only (no scale). grid 512, 256 threads, 2/SM.
// ==========================================================================
__global__ __launch_bounds__(256, 2) void outproj_kernel(float* __restrict__ out)
{
    extern __shared__ char smraw[];
    __nv_bfloat16* sAhi = (__nv_bfloat16*)smraw;
    __nv_bfloat16* sAlo = sAhi + 128 * LDB16;
    __nv_bfloat16* sBhi = sAlo + 128 * LDB16;
    __nv_bfloat16* sBlo = sBhi + 64 * LDB16;

    const int idx = blockIdx.x;
    const int m0 = (idx & 31) * 128;
    const int n0 = (idx >> 5) * 64;
    const int tid = threadIdx.x;
    const int warp = tid >> 5;
    const int wm = warp & 3;
    const int wn = warp >> 2;

    CBf acc[2][2];
#pragma unroll
    for (int i = 0; i < 2; i++)
#pragma unroll
        for (int j = 0; j < 2; j++) wmma::fill_fragment(acc[i][j], 0.0f);

    for (int k0 = 0; k0 < HID; k0 += 64) {
#pragma unroll
        for (int i = tid; i < 1024; i += 256) {
            int r = i >> 3, c8 = (i & 7) * 8;
            size_t g = (size_t)(m0 + r) * HID + k0 + c8;
            *(uint4*)&sAhi[r * LDB16 + c8] = *(const uint4*)&cat_hi[g];
            *(uint4*)&sAlo[r * LDB16 + c8] = *(const uint4*)&cat_lo[g];
        }
#pragma unroll
        for (int i = tid; i < 512; i += 256) {
            int r = i >> 3, c8 = (i & 7) * 8;
            size_t g = (size_t)(k0 + r) * HID + n0 + c8;
            *(uint4*)&sBhi[r * LDB16 + c8] = *(const uint4*)&wo_hi[g];
            *(uint4*)&sBlo[r * LDB16 + c8] = *(const uint4*)&wo_lo[g];
        }
        __syncthreads();

#pragma unroll
        for (int kk = 0; kk < 4; kk++) {
            ABf ahi[2], alo[2];
            BBfR bhi[2], blo[2];
#pragma unroll
            for (int i = 0; i < 2; i++) {
                wmma::load_matrix_sync(ahi[i], sAhi + (wm * 32 + i * 16) * LDB16 + kk * 16, LDB16);
                wmma::load_matrix_sync(alo[i], sAlo + (wm * 32 + i * 16) * LDB16 + kk * 16, LDB16);
            }
#pragma unroll
            for (int j = 0; j < 2; j++) {
                wmma::load_matrix_sync(bhi[j], sBhi + (kk * 16) * LDB16 + wn * 32 + j * 16, LDB16);
                wmma::load_matrix_sync(blo[j], sBlo + (kk * 16) * LDB16 + wn * 32 + j * 16, LDB16);
            }
#pragma unroll
            for (int i = 0; i < 2; i++)
#pragma unroll
                for (int j = 0; j < 2; j++)
                    wmma::mma_sync(acc[i][j], ahi[i], bhi[j], acc[i][j]);
#pragma unroll
            for (int i = 0; i < 2; i++)
#pragma unroll
                for (int j = 0; j < 2; j++)
                    wmma::mma_sync(acc[i][j], ahi[i], blo[j], acc[i][j]);
#pragma unroll
            for (int i = 0; i < 2; i++)
#pragma unroll
                for (int j = 0; j < 2; j++)
                    wmma::mma_sync(acc[i][j], alo[i], bhi[j], acc[i][j]);
        }
        __syncthreads();
    }

    float* obase = out + (size_t)m0 * HID + n0;
#pragma unroll
    for (int i = 0; i < 2; i++)
#pragma unroll
        for (int j = 0; j < 2; j++)
            wmma::store_matrix_sync(obase + (size_t)(wm * 32 + i * 16) * HID + wn * 32 + j * 16,
                                    acc[i][j], HID, wmma::mem_row_major);
}

// ==========================================================================
extern "C" void kernel_launch(void* const* d_in, const int* in_sizes, int n_in,
                              void* d_out, int out_size)
{
    const float* q  = (const float*)d_in[0];
    const float* k  = (const float*)d_in[1];
    const float* v  = (const float*)d_in[2];
    const float* Wq = (const float*)d_in[3];
    const float* Wk = (const float*)d_in[4];
    const float* Wv = (const float*)d_in[5];
    const float* Wo = (const float*)d_in[6];

    float* out  = (float*)d_out;
    float* attn = nullptr;
    const long long OUT_ELEMS  = (long long)MROWS * HID;
    const long long ATTN_ELEMS = (long long)B_ * H_ * S_ * S_;
    if ((long long)out_size >= OUT_ELEMS + ATTN_ELEMS)
        attn = out + OUT_ELEMS;

    const int gemm_smem = (128 + 64) * LDB16 * 2 * 2;        // 55296 bytes
    cudaFuncSetAttribute(proj_kernel,    cudaFuncAttributeMaxDynamicSharedMemorySize, PROJ_SMEM);
    cudaFuncSetAttribute(outproj_kernel, cudaFuncAttributeMaxDynamicSharedMemorySize, gemm_smem);
    cudaFuncSetAttribute(attn_kernel,    cudaFuncAttributeMaxDynamicSharedMemorySize, ATTN_SMEM);

    presplit_kernel<<<4096, 256>>>(q, k, v, Wq, Wk, Wv, Wo);

    dim3 g1(MROWS / 128, 3 * 8);
    proj_kernel<<<g1, 256, PROJ_SMEM>>>();

    dim3 g2(S_ / 128, B_ * H_);
    attn_kernel<<<g2, 256, ATTN_SMEM>>>(attn);

    outproj_kernel<<<512, 256, gemm_smem>>>(out);
}